// round 6
// baseline (speedup 1.0000x reference)
#include <cuda_runtime.h>

#define D      256
#define NDAY   7
#define NT     288
#define NC     (NDAY * NT)        // 2016 distinct (day, tod) combos
#define ROWS   (64 * 2048)        // B * S = 131072
#define MTILE  16                 // combos per m-block
#define NMB    (NC / MTILE)       // 126 m-blocks
#define KSPLIT 4                  // k-quarters
#define KQ     (D / KSPLIT)       // 64 k-values per CTA
#define NBLK_BUILD (NMB * KSPLIT) // 504
#define MPT    (MTILE / 2)        // 8 combos per thread (2 halves)

#define GATHER_BLOCKS  592        // 4 CTAs/SM * 148 SMs
#define GATHER_THREADS 256

// Packed f32x2 helpers (FFMA2 is only reachable via PTX).
__device__ __forceinline__ unsigned long long pk2(float lo, float hi) {
    unsigned long long r;
    asm("mov.b64 %0, {%1, %2};" : "=l"(r) : "f"(lo), "f"(hi));
    return r;
}
__device__ __forceinline__ unsigned long long fma2(
    unsigned long long a, unsigned long long b, unsigned long long c) {
    unsigned long long d;
    asm("fma.rn.f32x2 %0, %1, %2, %3;" : "=l"(d) : "l"(a), "l"(b), "l"(c));
    return d;
}
__device__ __forceinline__ float unpk_sum(unsigned long long v) {
    float lo, hi;
    asm("mov.b64 {%0, %1}, %2;" : "=f"(lo), "=f"(hi) : "l"(v));
    return lo + hi;
}

// Final table: one output row per (day,tod) combo. ~2 MB.
__device__ float g_table[NC * D];
// K-split partial sums. 4 x 2 MB.
__device__ float g_part[KSPLIT][NC * D];
// TE dtype flag: 1 = int64 layout, 0 = int32 layout.
__device__ int   g_te_is64;

// -------------------------------------------------------------------------
// Kernel 1: partial[ks][c][e] = sum_{k in quarter ks} relu_h[c][k] * W2[k][e]
//           (+ b2[e] folded into quarter 0)
// Grid: 126 m-blocks x 4 k-quarters = 504 CTAs, 256 threads.
// Thread: e = tid & 127 -> columns (e, e+128); half = tid>>7 -> 8 combos.
// Inner product packed along k with fma.rn.f32x2: acc lanes hold
// (even-k, odd-k) partials, horizontally summed at the end. Halves the
// fma-pipe instruction count vs scalar FFMA.
// Block 504: TE dtype detection.
// -------------------------------------------------------------------------
__global__ void __launch_bounds__(256) build_partial(
    const float* __restrict__ W1, const float* __restrict__ b1,
    const float* __restrict__ W2, const float* __restrict__ b2,
    const unsigned long long* __restrict__ TE64)
{
    const int bx = blockIdx.x;
    if (bx == NBLK_BUILD) {
        // TE values are 0..287: under int64 layout every high 32-bit word is
        // zero; under int32 it is a random index. P(false int64) ~ (1/288)^64.
        if (threadIdx.x < 32) {
            int lane = threadIdx.x;
            unsigned long long v = (TE64[lane] >> 32) | (TE64[lane + 32] >> 32);
            unsigned ballot = __ballot_sync(0xffffffffu, v != 0ULL);
            if (lane == 0) g_te_is64 = (ballot == 0u) ? 1 : 0;
        }
        return;
    }

    const int mb = bx >> 2;        // m-block 0..125
    const int ks = bx & 3;         // k-quarter 0..3
    const int c0 = mb * MTILE;
    const int k0 = ks * KQ;
    const int tid = threadIdx.x;

    __shared__ __align__(16) float h_sh[MTILE][KQ];   // 16 x 64 x 4B = 4 KB

    // Phase 1: h slice for this k-quarter. 16*64 = 1024 values, 256 threads.
    #pragma unroll
    for (int it = 0; it < (MTILE * KQ) / 256; it++) {
        int idx = it * 256 + tid;
        int m   = idx >> 6;            // /KQ
        int kk  = idx & (KQ - 1);
        int c   = c0 + m;
        int day = c / NT;
        int tod = c - day * NT;
        int k   = k0 + kk;
        float v = W1[day * D + k] + W1[(NDAY + tod) * D + k] + b1[k];
        h_sh[m][kk] = fmaxf(v, 0.0f);
    }
    __syncthreads();

    // Phase 2: packed GEMM. Thread -> columns (e, e+128), combos m0..m0+7.
    const int e    = tid & 127;
    const int half = tid >> 7;
    const int m0   = half * MPT;

    unsigned long long acc0[MPT];   // column e       (even-k, odd-k) partials
    unsigned long long acc1[MPT];   // column e + 128
    {
        const float i0 = (ks == 0) ? b2[e]       : 0.0f;
        const float i1 = (ks == 0) ? b2[e + 128] : 0.0f;
        unsigned long long z0 = pk2(i0, 0.0f);
        unsigned long long z1 = pk2(i1, 0.0f);
        #pragma unroll
        for (int m = 0; m < MPT; m++) { acc0[m] = z0; acc1[m] = z1; }
    }

    #pragma unroll 4
    for (int kk = 0; kk < KQ; kk += 4) {
        const float* w = W2 + (size_t)(k0 + kk) * D + e;
        unsigned long long pa01 = pk2(w[0 * D],       w[1 * D]);
        unsigned long long pa23 = pk2(w[2 * D],       w[3 * D]);
        unsigned long long pb01 = pk2(w[0 * D + 128], w[1 * D + 128]);
        unsigned long long pb23 = pk2(w[2 * D + 128], w[3 * D + 128]);
        #pragma unroll
        for (int m = 0; m < MPT; m++) {
            // One LDS.128 = two pre-packed f32x2 operands (h[k],h[k+1]) etc.
            ulonglong2 h2 = *reinterpret_cast<const ulonglong2*>(&h_sh[m0 + m][kk]);
            acc0[m] = fma2(h2.x, pa01, acc0[m]);
            acc0[m] = fma2(h2.y, pa23, acc0[m]);
            acc1[m] = fma2(h2.x, pb01, acc1[m]);
            acc1[m] = fma2(h2.y, pb23, acc1[m]);
        }
    }

    float* __restrict__ part = g_part[ks];
    #pragma unroll
    for (int m = 0; m < MPT; m++) {
        part[(size_t)(c0 + m0 + m) * D + e]       = unpk_sum(acc0[m]);
        part[(size_t)(c0 + m0 + m) * D + e + 128] = unpk_sum(acc1[m]);
    }
}

// -------------------------------------------------------------------------
// Kernel 2: g_table = sum of 4 partials. 129024 float4 = 504 x 256 x 1.
// -------------------------------------------------------------------------
__global__ void __launch_bounds__(256) reduce_parts()
{
    int i = blockIdx.x * 256 + threadIdx.x;
    const float4* p0 = reinterpret_cast<const float4*>(g_part[0]);
    const float4* p1 = reinterpret_cast<const float4*>(g_part[1]);
    const float4* p2 = reinterpret_cast<const float4*>(g_part[2]);
    const float4* p3 = reinterpret_cast<const float4*>(g_part[3]);
    float4 a = p0[i], b = p1[i], c = p2[i], d = p3[i];
    float4 r;
    r.x = (a.x + b.x) + (c.x + d.x);
    r.y = (a.y + b.y) + (c.y + d.y);
    r.z = (a.z + b.z) + (c.z + d.z);
    r.w = (a.w + b.w) + (c.w + d.w);
    reinterpret_cast<float4*>(g_table)[i] = r;
}

// -------------------------------------------------------------------------
// Kernel 3: out[row] = table[day*NT + tod]. Persistent, one warp per row.
// Streaming stores keep the 134 MB output from churning L2 against the
// hot 2 MB table.
// -------------------------------------------------------------------------
__global__ void __launch_bounds__(GATHER_THREADS) gather_out(
    const void* __restrict__ TEp, float* __restrict__ out)
{
    const int lane    = threadIdx.x & 31;
    const int warp    = blockIdx.x * (GATHER_THREADS >> 5) + (threadIdx.x >> 5);
    const int n_warps = GATHER_BLOCKS * (GATHER_THREADS >> 5);
    const bool is64   = (g_te_is64 != 0);

    const longlong2* __restrict__ TE8 = (const longlong2*)TEp;
    const int2*      __restrict__ TE4 = (const int2*)TEp;

    int row = warp;
    if (row >= ROWS) return;

    int t0, t1;
    if (is64) { longlong2 te = TE8[row]; t0 = (int)te.x; t1 = (int)te.y; }
    else      { int2      te = TE4[row]; t0 = te.x;      t1 = te.y;      }

    while (true) {
        int next = row + n_warps;
        int n0 = 0, n1 = 0;
        if (next < ROWS) {
            if (is64) { longlong2 te = TE8[next]; n0 = (int)te.x; n1 = (int)te.y; }
            else      { int2      te = TE4[next]; n0 = te.x;      n1 = te.y;      }
        }

        int day = t0 % NDAY; day += (day >> 31) & NDAY;
        int tod = t1 % NT;   tod += (tod >> 31) & NT;
        int c   = day * NT + tod;

        const float4* __restrict__ src =
            reinterpret_cast<const float4*>(g_table + (size_t)c * D);
        float4* __restrict__ dst =
            reinterpret_cast<float4*>(out + (size_t)row * D);

        float4 v0 = src[lane];
        float4 v1 = src[lane + 32];
        __stcs(dst + lane,      v0);
        __stcs(dst + lane + 32, v1);

        if (next >= ROWS) break;
        row = next; t0 = n0; t1 = n1;
    }
}

// -------------------------------------------------------------------------
// Launch. Inputs resolved by element count:
//   TE = d_in[0]; W1: 295*256 = 75520; W2: 256*256 = 65536; b1/b2: 256 each.
// -------------------------------------------------------------------------
extern "C" void kernel_launch(void* const* d_in, const int* in_sizes, int n_in,
                              void* d_out, int out_size)
{
    const void* TE = d_in[0];
    const float* W1 = nullptr;
    const float* b1 = nullptr;
    const float* W2 = nullptr;
    const float* b2 = nullptr;

    for (int j = 1; j < n_in; j++) {
        int sz = in_sizes[j];
        if (sz == (NDAY + NT) * D) {
            W1 = (const float*)d_in[j];
        } else if (sz == D * D) {
            W2 = (const float*)d_in[j];
        } else if (sz == D) {
            if (!b1) b1 = (const float*)d_in[j];
            else     b2 = (const float*)d_in[j];
        }
    }
    if (!W1 || !b1 || !W2 || !b2) return;

    float* out = (float*)d_out;

    build_partial<<<NBLK_BUILD + 1, 256>>>(W1, b1, W2, b2,
                                           (const unsigned long long*)TE);
    reduce_parts<<<NBLK_BUILD, 256>>>();
    gather_out<<<GATHER_BLOCKS, GATHER_THREADS>>>(TE, out);
}